// round 2
// baseline (speedup 1.0000x reference)
#include <cuda_runtime.h>
#include <math.h>

// Problem constants (shapes fixed by the dataset)
#define BATCH 32
#define TLEN 64
#define SLEN 400
#define DIM 1024
#define VOCAB 32000
#define EXT 600
#define BT (BATCH * TLEN)      // 2048 rows
#define OUTW (VOCAB + EXT)     // 32600 output columns
#define PAD_IDX 1

// Scratch (device globals: no allocation allowed)
__device__ float g_pcopy[BT];
__device__ float g_rowmax[BT];
__device__ int   g_idx[SLEN * BATCH];

// ---------------------------------------------------------------------------
__global__ void init_kernel() {
    int i = blockIdx.x * blockDim.x + threadIdx.x;
    if (i < BT) g_rowmax[i] = -INFINITY;
}

// ---------------------------------------------------------------------------
// p_copy[r] = sigmoid(hidden[r] . Wc + bc)
__global__ void pcopy_kernel(const float* __restrict__ hidden,
                             const float* __restrict__ Wc,
                             const float* __restrict__ bc) {
    int r = blockIdx.x;
    const float* h = hidden + (size_t)r * DIM;
    float s = 0.f;
    for (int k = threadIdx.x; k < DIM; k += blockDim.x) s += h[k] * Wc[k];
    __shared__ float red[32];
    for (int o = 16; o; o >>= 1) s += __shfl_down_sync(0xffffffffu, s, o);
    if ((threadIdx.x & 31) == 0) red[threadIdx.x >> 5] = s;
    __syncthreads();
    if (threadIdx.x < 32) {
        float t = (threadIdx.x < (blockDim.x >> 5)) ? red[threadIdx.x] : 0.f;
        for (int o = 16; o; o >>= 1) t += __shfl_down_sync(0xffffffffu, t, o);
        if (threadIdx.x == 0)
            g_pcopy[r] = 1.f / (1.f + __expf(-(t + bc[0])));
    }
}

// ---------------------------------------------------------------------------
// idx[s*B+b] = argmax_e src_map[s][b][e]   (first-max on tie, like jnp.argmax)
__global__ void argmax_kernel(const float* __restrict__ src_map) {
    int task = blockIdx.x * 8 + (threadIdx.x >> 5);   // 8 warps per block
    if (task >= SLEN * BATCH) return;
    int lane = threadIdx.x & 31;
    const float* p = src_map + (size_t)task * EXT;
    float best = -INFINITY; int bi = EXT;
    for (int e = lane; e < EXT; e += 32) {
        float v = p[e];
        if (v > best) { best = v; bi = e; }
    }
    for (int off = 16; off; off >>= 1) {
        float ov = __shfl_down_sync(0xffffffffu, best, off);
        int   oi = __shfl_down_sync(0xffffffffu, bi, off);
        if (ov > best || (ov == best && oi < bi)) { best = ov; bi = oi; }
    }
    if (lane == 0) g_idx[task] = bi;
}

// ---------------------------------------------------------------------------
__device__ __forceinline__ void atomicMaxFloat(float* addr, float val) {
    int old = __float_as_int(*addr);
    while (__int_as_float(old) < val) {
        int assumed = old;
        old = atomicCAS((int*)addr, assumed, __float_as_int(val));
        if (old == assumed) break;
    }
}

// ---------------------------------------------------------------------------
// logits = hidden @ W^T + b, PAD column -> -inf, written into out[:, 0:VOCAB].
// Epilogue also maintains per-row max via atomics.
#define BM 128
#define BN 128
#define BKK 8

__global__ __launch_bounds__(256, 2)
void gemm_kernel(const float* __restrict__ A,    // (BT, DIM)
                 const float* __restrict__ Wm,   // (VOCAB, DIM)
                 const float* __restrict__ bias, // (VOCAB)
                 float* __restrict__ out) {
    __shared__ float As[BKK][BM + 4];
    __shared__ float Bs[BKK][BN + 4];
    const int tid = threadIdx.x;
    const int tx = tid & 15, ty = tid >> 4;
    const int bm = blockIdx.y * BM;
    const int bn = blockIdx.x * BN;
    const int lr = tid >> 1;           // 0..127
    const int lk = (tid & 1) << 2;     // 0 or 4
    const float* Ap = A  + (size_t)(bm + lr) * DIM + lk;
    const float* Bp = Wm + (size_t)(bn + lr) * DIM + lk;

    float acc[8][8];
#pragma unroll
    for (int i = 0; i < 8; i++)
#pragma unroll
        for (int j = 0; j < 8; j++) acc[i][j] = 0.f;

    for (int k0 = 0; k0 < DIM; k0 += BKK) {
        float4 a4 = *(const float4*)(Ap + k0);
        float4 b4 = *(const float4*)(Bp + k0);
        As[lk + 0][lr] = a4.x; As[lk + 1][lr] = a4.y;
        As[lk + 2][lr] = a4.z; As[lk + 3][lr] = a4.w;
        Bs[lk + 0][lr] = b4.x; Bs[lk + 1][lr] = b4.y;
        Bs[lk + 2][lr] = b4.z; Bs[lk + 3][lr] = b4.w;
        __syncthreads();
#pragma unroll
        for (int kk = 0; kk < BKK; kk++) {
            float a[8], b[8];
            *(float4*)&a[0] = *(const float4*)&As[kk][ty * 8];
            *(float4*)&a[4] = *(const float4*)&As[kk][ty * 8 + 4];
            *(float4*)&b[0] = *(const float4*)&Bs[kk][tx * 8];
            *(float4*)&b[4] = *(const float4*)&Bs[kk][tx * 8 + 4];
#pragma unroll
            for (int i = 0; i < 8; i++)
#pragma unroll
                for (int j = 0; j < 8; j++)
                    acc[i][j] = fmaf(a[i], b[j], acc[i][j]);
        }
        __syncthreads();
    }

#pragma unroll
    for (int i = 0; i < 8; i++) {
        int m = bm + ty * 8 + i;
        float* orow = out + (size_t)m * OUTW;
        float rmax = -INFINITY;
#pragma unroll
        for (int j = 0; j < 8; j++) {
            int n = bn + tx * 8 + j;
            float v = acc[i][j] + __ldg(&bias[n]);
            if (n == PAD_IDX) v = -INFINITY;
            orow[n] = v;
            rmax = fmaxf(rmax, v);
        }
        atomicMaxFloat(&g_rowmax[m], rmax);
    }
}

// ---------------------------------------------------------------------------
// In-place softmax over out[r, 0:VOCAB], scaled by (1 - p_copy[r]).
__global__ __launch_bounds__(512)
void softmax_kernel(float* __restrict__ out) {
    int r = blockIdx.x;
    float m = g_rowmax[r];
    float* row = out + (size_t)r * OUTW;
    float s = 0.f;
    for (int v = threadIdx.x; v < VOCAB; v += blockDim.x) {
        float l = row[v];
        float e = (v == PAD_IDX) ? 0.f : __expf(l - m);
        row[v] = e;
        s += e;
    }
    __shared__ float red[32];
    for (int o = 16; o; o >>= 1) s += __shfl_down_sync(0xffffffffu, s, o);
    if ((threadIdx.x & 31) == 0) red[threadIdx.x >> 5] = s;
    __syncthreads();
    if (threadIdx.x < 32) {
        float t = (threadIdx.x < (blockDim.x >> 5)) ? red[threadIdx.x] : 0.f;
        for (int o = 16; o; o >>= 1) t += __shfl_down_sync(0xffffffffu, t, o);
        if (threadIdx.x == 0) red[0] = t;
    }
    __syncthreads();
    float scale = (1.f - g_pcopy[r]) / red[0];
    for (int v = threadIdx.x; v < VOCAB; v += blockDim.x)
        row[v] *= scale;
}

// ---------------------------------------------------------------------------
// copy_prob: out[r, VOCAB + c] = p_copy[r] * sum_{s: idx[s,b]==c} attn[r,s]
__global__ void copy_kernel(const float* __restrict__ attn,
                            float* __restrict__ out) {
    int r = blockIdx.x;
    int b = r % BATCH;               // rows are tlen-major: r = t*BATCH + b
    __shared__ float bins[EXT];
    for (int c = threadIdx.x; c < EXT; c += blockDim.x) bins[c] = 0.f;
    __syncthreads();
    const float* arow = attn + (size_t)r * SLEN;
    for (int s = threadIdx.x; s < SLEN; s += blockDim.x)
        atomicAdd(&bins[g_idx[s * BATCH + b]], arow[s]);
    __syncthreads();
    float pc = g_pcopy[r];
    float* orow = out + (size_t)r * OUTW + VOCAB;
    for (int c = threadIdx.x; c < EXT; c += blockDim.x)
        orow[c] = bins[c] * pc;
}

// ---------------------------------------------------------------------------
extern "C" void kernel_launch(void* const* d_in, const int* in_sizes, int n_in,
                              void* d_out, int out_size) {
    const float* hidden = (const float*)d_in[0];
    const float* attn   = (const float*)d_in[1];
    const float* srcmap = (const float*)d_in[2];
    const float* W      = (const float*)d_in[3];
    const float* b      = (const float*)d_in[4];
    const float* Wc     = (const float*)d_in[5];
    const float* bc     = (const float*)d_in[6];
    float* out = (float*)d_out;

    init_kernel<<<(BT + 255) / 256, 256>>>();
    pcopy_kernel<<<BT, 256>>>(hidden, Wc, bc);
    argmax_kernel<<<(SLEN * BATCH + 7) / 8, 256>>>(srcmap);
    dim3 grid(VOCAB / BN, BT / BM);
    gemm_kernel<<<grid, 256>>>(hidden, W, b, out);
    softmax_kernel<<<BT, 512>>>(out);
    copy_kernel<<<BT, 256>>>(attn, out);
}

// round 4
// speedup vs baseline: 4.3945x; 4.3945x over previous
#include <cuda_runtime.h>
#include <math.h>
#include <stdint.h>

// ---------------- problem constants ----------------
#define BATCH 32
#define TLEN 64
#define SLEN 400
#define DIM 1024
#define VOCAB 32000
#define EXT 600
#define BT (BATCH * TLEN)      // 2048 rows
#define OUTW (VOCAB + EXT)     // 32600
#define PAD_IDX 1

// ---------------- GEMM tiling ----------------
#define BM 128
#define BN 128
#define BK 32
#define STAGES 3
#define NCHUNK (DIM / BK)          // 32
#define TILE_BYTES 16384           // 128 rows x 128B
#define STAGE_BYTES (2 * TILE_BYTES)
#define SMEM_BYTES (STAGES * STAGE_BYTES)   // 96 KB

// ---------------- scratch (device globals; no allocation allowed) ----------
__device__ float g_pcopy[BT];
__device__ float g_rowsum[BT];
__device__ int   g_idx[SLEN * BATCH];
__device__ float g_Wc[(size_t)VOCAB * DIM];   // tf32-rounded W
__device__ float g_Ac[(size_t)BT * DIM];      // tf32-rounded hidden

// ---------------- helpers ----------------
__device__ __forceinline__ uint32_t smem_u32(const void* p) {
    uint32_t a;
    asm("{ .reg .u64 t; cvta.to.shared.u64 t, %1; cvt.u32.u64 %0, t; }"
        : "=r"(a) : "l"(p));
    return a;
}

__device__ __forceinline__ void cpasync16(uint32_t dst, const void* src) {
    asm volatile("cp.async.cg.shared.global [%0], [%1], 16;"
                 :: "r"(dst), "l"(src) : "memory");
}

__device__ __forceinline__ void ldm_x4(uint32_t* r, uint32_t addr) {
    asm volatile("ldmatrix.sync.aligned.m8n8.x4.shared.b16 {%0,%1,%2,%3}, [%4];"
                 : "=r"(r[0]), "=r"(r[1]), "=r"(r[2]), "=r"(r[3]) : "r"(addr));
}

__device__ __forceinline__ void mma_tf32(float* c, const uint32_t* a,
                                         uint32_t b0, uint32_t b1) {
    asm volatile(
        "mma.sync.aligned.m16n8k8.row.col.f32.tf32.tf32.f32 "
        "{%0,%1,%2,%3}, {%4,%5,%6,%7}, {%8,%9}, {%0,%1,%2,%3};"
        : "+f"(c[0]), "+f"(c[1]), "+f"(c[2]), "+f"(c[3])
        : "r"(a[0]), "r"(a[1]), "r"(a[2]), "r"(a[3]), "r"(b0), "r"(b1));
}

// ---------------------------------------------------------------------------
__global__ void init_kernel() {
    int i = blockIdx.x * blockDim.x + threadIdx.x;
    if (i < BT) g_rowsum[i] = 0.f;
}

// fp32 -> tf32 (round-to-nearest) copy
__global__ void cvt_tf32_kernel(const float4* __restrict__ src,
                                float4* __restrict__ dst, int n4) {
    int stride = gridDim.x * blockDim.x;
    for (int i = blockIdx.x * blockDim.x + threadIdx.x; i < n4; i += stride) {
        float4 v = src[i];
        uint32_t a, b, c, d;
        asm("cvt.rna.tf32.f32 %0, %1;" : "=r"(a) : "f"(v.x));
        asm("cvt.rna.tf32.f32 %0, %1;" : "=r"(b) : "f"(v.y));
        asm("cvt.rna.tf32.f32 %0, %1;" : "=r"(c) : "f"(v.z));
        asm("cvt.rna.tf32.f32 %0, %1;" : "=r"(d) : "f"(v.w));
        float4 o;
        o.x = __uint_as_float(a); o.y = __uint_as_float(b);
        o.z = __uint_as_float(c); o.w = __uint_as_float(d);
        dst[i] = o;
    }
}

// ---------------------------------------------------------------------------
__global__ void pcopy_kernel(const float* __restrict__ hidden,
                             const float* __restrict__ Wc,
                             const float* __restrict__ bc) {
    int r = blockIdx.x;
    const float* h = hidden + (size_t)r * DIM;
    float s = 0.f;
    for (int k = threadIdx.x; k < DIM; k += blockDim.x) s += h[k] * Wc[k];
    __shared__ float red[32];
    for (int o = 16; o; o >>= 1) s += __shfl_down_sync(0xffffffffu, s, o);
    if ((threadIdx.x & 31) == 0) red[threadIdx.x >> 5] = s;
    __syncthreads();
    if (threadIdx.x < 32) {
        float t = (threadIdx.x < (blockDim.x >> 5)) ? red[threadIdx.x] : 0.f;
        for (int o = 16; o; o >>= 1) t += __shfl_down_sync(0xffffffffu, t, o);
        if (threadIdx.x == 0)
            g_pcopy[r] = 1.f / (1.f + __expf(-(t + bc[0])));
    }
}

__global__ void argmax_kernel(const float* __restrict__ src_map) {
    int task = blockIdx.x * 8 + (threadIdx.x >> 5);
    if (task >= SLEN * BATCH) return;
    int lane = threadIdx.x & 31;
    const float* p = src_map + (size_t)task * EXT;
    float best = -INFINITY; int bi = EXT;
    for (int e = lane; e < EXT; e += 32) {
        float v = p[e];
        if (v > best) { best = v; bi = e; }
    }
    for (int off = 16; off; off >>= 1) {
        float ov = __shfl_down_sync(0xffffffffu, best, off);
        int   oi = __shfl_down_sync(0xffffffffu, bi, off);
        if (ov > best || (ov == best && oi < bi)) { best = ov; bi = oi; }
    }
    if (lane == 0) g_idx[task] = bi;
}

// ---------------------------------------------------------------------------
// tf32 mma.sync GEMM: out[m, n0:n0+BN] = exp(A.W^T + b) (PAD col -> 0),
// partial row sums into g_rowsum.
extern __shared__ char dyn_smem[];

__global__ __launch_bounds__(256, 2)
void gemm_tc_kernel(const float* __restrict__ A,    // g_Ac (BT, DIM)
                    const float* __restrict__ W,    // g_Wc (VOCAB, DIM)
                    const float* __restrict__ bias,
                    float* __restrict__ out) {
    const uint32_t sbase = smem_u32(dyn_smem);
    const int tid  = threadIdx.x;
    const int wid  = tid >> 5;
    const int lane = tid & 31;
    const int warp_m = wid >> 2;       // 0..1  (64-row slice)
    const int warp_n = wid & 3;        // 0..3  (32-col slice)
    const int n0 = blockIdx.x * BN;
    const int m0 = blockIdx.y * BM;

    const float* Abase = A + (size_t)m0 * DIM;
    const float* Wbase = W + (size_t)n0 * DIM;

    // global->smem loader: 2048 16B chunks per stage (A then B), 8 per thread
    const int ld_row = tid >> 1;                    // 0..127
    const int ld_cc0 = (tid & 1) * 4;               // chunk pair base? (see below)
    (void)ld_cc0;

    auto load_stage = [&](int j) {
        uint32_t s = sbase + (uint32_t)(j % STAGES) * STAGE_BYTES;
#pragma unroll
        for (int i = 0; i < 4; i++) {
            int ch  = i * 256 + tid;                // 0..1023
            int row = ch >> 3;                      // 0..127
            int cc  = ch & 7;                       // 16B chunk in 128B row
            uint32_t off = (uint32_t)(row * 128) + (uint32_t)((cc * 16) ^ ((row & 7) << 4));
            const float* ga = Abase + (size_t)row * DIM + j * BK + cc * 4;
            const float* gw = Wbase + (size_t)row * DIM + j * BK + cc * 4;
            cpasync16(s + off, ga);
            cpasync16(s + TILE_BYTES + off, gw);
        }
        asm volatile("cp.async.commit_group;" ::: "memory");
    };

    float acc[4][4][4];
#pragma unroll
    for (int i = 0; i < 4; i++)
#pragma unroll
        for (int j = 0; j < 4; j++)
#pragma unroll
            for (int q = 0; q < 4; q++) acc[i][j][q] = 0.f;

    // precompute per-lane ldmatrix row addressing
    const int a_tile = lane >> 3, a_r = lane & 7;
    // A: row within CTA tile for m-fragment; seg selects k 0-3 / 4-7 halves
    const int a_row0 = warp_m * 64 + (a_tile & 1) * 8 + a_r;
    const int a_seg  = (a_tile >> 1) * 16;
    // B: rows are n; tile0/1 = n 0-7 (k lo/hi), tile2/3 = n 8-15
    const int b_row0 = warp_n * 32 + (a_tile >> 1) * 8 + a_r;
    const int b_seg  = (a_tile & 1) * 16;

    for (int j = 0; j < STAGES; j++) load_stage(j);

    for (int j = 0; j < NCHUNK; j++) {
        if (j < NCHUNK - 2)
            asm volatile("cp.async.wait_group %0;" :: "n"(STAGES - 1) : "memory");
        else if (j == NCHUNK - 2)
            asm volatile("cp.async.wait_group %0;" :: "n"(1) : "memory");
        else
            asm volatile("cp.async.wait_group %0;" :: "n"(0) : "memory");
        __syncthreads();

        uint32_t sA = sbase + (uint32_t)(j % STAGES) * STAGE_BYTES;
        uint32_t sB = sA + TILE_BYTES;

#pragma unroll
        for (int ks = 0; ks < 4; ks++) {
            uint32_t a[4][4];
#pragma unroll
            for (int mt = 0; mt < 4; mt++) {
                int row = a_row0 + mt * 16;
                uint32_t bcol = (uint32_t)((ks * 32 + a_seg) ^ ((row & 7) << 4));
                ldm_x4(a[mt], sA + (uint32_t)(row * 128) + bcol);
            }
            uint32_t bf[2][4];
#pragma unroll
            for (int np = 0; np < 2; np++) {
                int row = b_row0 + np * 16;
                uint32_t bcol = (uint32_t)((ks * 32 + b_seg) ^ ((row & 7) << 4));
                ldm_x4(bf[np], sB + (uint32_t)(row * 128) + bcol);
            }
#pragma unroll
            for (int mt = 0; mt < 4; mt++)
#pragma unroll
                for (int nt = 0; nt < 4; nt++)
                    mma_tf32(acc[mt][nt], a[mt],
                             bf[nt >> 1][(nt & 1) * 2], bf[nt >> 1][(nt & 1) * 2 + 1]);
        }
        __syncthreads();
        if (j + STAGES < NCHUNK) load_stage(j + STAGES);
    }

    // ---- epilogue: bias + exp + store + row-sum ----
    const int g = lane >> 2;           // group id 0..7
    const int q4 = lane & 3;
    float rs_lo[4], rs_hi[4];
#pragma unroll
    for (int mt = 0; mt < 4; mt++) { rs_lo[mt] = 0.f; rs_hi[mt] = 0.f; }

#pragma unroll
    for (int mt = 0; mt < 4; mt++) {
        int m_lo = m0 + warp_m * 64 + mt * 16 + g;
        int m_hi = m_lo + 8;
        float* row_lo = out + (size_t)m_lo * OUTW;
        float* row_hi = out + (size_t)m_hi * OUTW;
#pragma unroll
        for (int nt = 0; nt < 4; nt++) {
            int n = n0 + warp_n * 32 + nt * 8 + q4 * 2;
            float b0 = __ldg(&bias[n]);
            float b1 = __ldg(&bias[n + 1]);
            float e0 = __expf(acc[mt][nt][0] + b0);
            float e1 = __expf(acc[mt][nt][1] + b1);
            float e2 = __expf(acc[mt][nt][2] + b0);
            float e3 = __expf(acc[mt][nt][3] + b1);
            if (n == PAD_IDX)     { e0 = 0.f; e2 = 0.f; }
            if (n + 1 == PAD_IDX) { e1 = 0.f; e3 = 0.f; }
            *(float2*)(row_lo + n) = make_float2(e0, e1);
            *(float2*)(row_hi + n) = make_float2(e2, e3);
            rs_lo[mt] += e0 + e1;
            rs_hi[mt] += e2 + e3;
        }
    }
    // reduce across the 4 lanes sharing each row, then one atomic per row
#pragma unroll
    for (int mt = 0; mt < 4; mt++) {
        float lo = rs_lo[mt], hi = rs_hi[mt];
        lo += __shfl_xor_sync(0xffffffffu, lo, 1);
        lo += __shfl_xor_sync(0xffffffffu, lo, 2);
        hi += __shfl_xor_sync(0xffffffffu, hi, 1);
        hi += __shfl_xor_sync(0xffffffffu, hi, 2);
        if (q4 == 0) {
            int m_lo = m0 + warp_m * 64 + mt * 16 + g;
            atomicAdd(&g_rowsum[m_lo], lo);
            atomicAdd(&g_rowsum[m_lo + 8], hi);
        }
    }
}

// ---------------------------------------------------------------------------
// out[r, 0:VOCAB] *= (1 - pcopy[r]) / rowsum[r]
__global__ __launch_bounds__(512)
void scale_kernel(float* __restrict__ out) {
    int r = blockIdx.x;
    float s = (1.f - g_pcopy[r]) / g_rowsum[r];
    float4* row = (float4*)(out + (size_t)r * OUTW);
    for (int i = threadIdx.x; i < VOCAB / 4; i += blockDim.x) {
        float4 v = row[i];
        v.x *= s; v.y *= s; v.z *= s; v.w *= s;
        row[i] = v;
    }
}

// ---------------------------------------------------------------------------
__global__ void copy_kernel(const float* __restrict__ attn,
                            float* __restrict__ out) {
    int r = blockIdx.x;
    int b = r % BATCH;               // rows are tlen-major: r = t*BATCH + b
    __shared__ float bins[EXT];
    for (int c = threadIdx.x; c < EXT; c += blockDim.x) bins[c] = 0.f;
    __syncthreads();
    const float* arow = attn + (size_t)r * SLEN;
    for (int s = threadIdx.x; s < SLEN; s += blockDim.x)
        atomicAdd(&bins[g_idx[s * BATCH + b]], arow[s]);
    __syncthreads();
    float pc = g_pcopy[r];
    float* orow = out + (size_t)r * OUTW + VOCAB;
    for (int c = threadIdx.x; c < EXT; c += blockDim.x)
        orow[c] = bins[c] * pc;
}

// ---------------------------------------------------------------------------
extern "C" void kernel_launch(void* const* d_in, const int* in_sizes, int n_in,
                              void* d_out, int out_size) {
    const float* hidden = (const float*)d_in[0];
    const float* attn   = (const float*)d_in[1];
    const float* srcmap = (const float*)d_in[2];
    const float* W      = (const float*)d_in[3];
    const float* b      = (const float*)d_in[4];
    const float* Wc     = (const float*)d_in[5];
    const float* bc     = (const float*)d_in[6];
    float* out = (float*)d_out;

    cudaFuncSetAttribute(gemm_tc_kernel,
                         cudaFuncAttributeMaxDynamicSharedMemorySize, SMEM_BYTES);

    float *Wcv, *Acv;
    cudaGetSymbolAddress((void**)&Wcv, g_Wc);
    cudaGetSymbolAddress((void**)&Acv, g_Ac);

    init_kernel<<<(BT + 255) / 256, 256>>>();
    cvt_tf32_kernel<<<2048, 256>>>((const float4*)W, (float4*)Wcv,
                                   (int)((size_t)VOCAB * DIM / 4));
    cvt_tf32_kernel<<<1024, 256>>>((const float4*)hidden, (float4*)Acv,
                                   (int)((size_t)BT * DIM / 4));
    pcopy_kernel<<<BT, 256>>>(hidden, Wc, bc);
    argmax_kernel<<<(SLEN * BATCH + 7) / 8, 256>>>(srcmap);

    dim3 grid(VOCAB / BN, BT / BM);   // (250, 16)
    gemm_tc_kernel<<<grid, 256, SMEM_BYTES>>>(Acv, Wcv, b, out);

    scale_kernel<<<BT, 512>>>(out);
    copy_kernel<<<BT, 256>>>(attn, out);
}

// round 5
// speedup vs baseline: 6.4758x; 1.4736x over previous
#include <cuda_runtime.h>
#include <cuda_bf16.h>
#include <math.h>
#include <stdint.h>

// ---------------- problem constants ----------------
#define BATCH 32
#define TLEN 64
#define SLEN 400
#define DIM 1024
#define VOCAB 32000
#define EXT 600
#define BT (BATCH * TLEN)      // 2048 rows
#define OUTW (VOCAB + EXT)     // 32600
#define PAD_IDX 1

// ---------------- GEMM tiling (bf16) ----------------
#define BM 256
#define BN 128
#define BK 64                       // 64 bf16 = 128B rows
#define STAGES 3
#define NCHUNK (DIM / BK)           // 16
#define A_TILE_BYTES (BM * 128)     // 32 KB
#define B_TILE_BYTES (BN * 128)     // 16 KB
#define STAGE_BYTES (A_TILE_BYTES + B_TILE_BYTES)  // 48 KB
#define SMEM_BYTES (STAGES * STAGE_BYTES)          // 144 KB

// ---------------- scratch (device globals; no allocation allowed) ----------
__device__ float g_pcopy[BT];
__device__ float g_rowsum[BT];
__device__ int   g_idx[SLEN * BATCH];
__device__ __nv_bfloat16 g_Wb[(size_t)VOCAB * DIM];   // bf16 W (64 MB)
__device__ __nv_bfloat16 g_Ab[(size_t)BT * DIM];      // bf16 hidden (4 MB)

// ---------------- helpers ----------------
__device__ __forceinline__ uint32_t smem_u32(const void* p) {
    uint32_t a;
    asm("{ .reg .u64 t; cvta.to.shared.u64 t, %1; cvt.u32.u64 %0, t; }"
        : "=r"(a) : "l"(p));
    return a;
}

__device__ __forceinline__ void cpasync16(uint32_t dst, const void* src) {
    asm volatile("cp.async.cg.shared.global [%0], [%1], 16;"
                 :: "r"(dst), "l"(src) : "memory");
}

__device__ __forceinline__ void ldm_x4(uint32_t* r, uint32_t addr) {
    asm volatile("ldmatrix.sync.aligned.m8n8.x4.shared.b16 {%0,%1,%2,%3}, [%4];"
                 : "=r"(r[0]), "=r"(r[1]), "=r"(r[2]), "=r"(r[3]) : "r"(addr));
}

__device__ __forceinline__ void mma_bf16(float* c, const uint32_t* a,
                                         uint32_t b0, uint32_t b1) {
    asm volatile(
        "mma.sync.aligned.m16n8k16.row.col.f32.bf16.bf16.f32 "
        "{%0,%1,%2,%3}, {%4,%5,%6,%7}, {%8,%9}, {%0,%1,%2,%3};"
        : "+f"(c[0]), "+f"(c[1]), "+f"(c[2]), "+f"(c[3])
        : "r"(a[0]), "r"(a[1]), "r"(a[2]), "r"(a[3]), "r"(b0), "r"(b1));
}

// ---------------------------------------------------------------------------
__global__ void init_kernel() {
    int i = blockIdx.x * blockDim.x + threadIdx.x;
    if (i < BT) g_rowsum[i] = 0.f;
}

// fp32 -> bf16 conversion (vectorized: float4 in, 8B out)
__global__ void cvt_bf16_kernel(const float4* __restrict__ src,
                                uint2* __restrict__ dst, int n4) {
    int stride = gridDim.x * blockDim.x;
    for (int i = blockIdx.x * blockDim.x + threadIdx.x; i < n4; i += stride) {
        float4 v = src[i];
        __nv_bfloat162 lo = __floats2bfloat162_rn(v.x, v.y);
        __nv_bfloat162 hi = __floats2bfloat162_rn(v.z, v.w);
        uint2 o;
        o.x = *(uint32_t*)&lo;
        o.y = *(uint32_t*)&hi;
        dst[i] = o;
    }
}

// ---------------------------------------------------------------------------
__global__ void pcopy_kernel(const float* __restrict__ hidden,
                             const float* __restrict__ Wc,
                             const float* __restrict__ bc) {
    int r = blockIdx.x;
    const float* h = hidden + (size_t)r * DIM;
    float s = 0.f;
    for (int k = threadIdx.x; k < DIM; k += blockDim.x) s += h[k] * Wc[k];
    __shared__ float red[32];
    for (int o = 16; o; o >>= 1) s += __shfl_down_sync(0xffffffffu, s, o);
    if ((threadIdx.x & 31) == 0) red[threadIdx.x >> 5] = s;
    __syncthreads();
    if (threadIdx.x < 32) {
        float t = (threadIdx.x < (blockDim.x >> 5)) ? red[threadIdx.x] : 0.f;
        for (int o = 16; o; o >>= 1) t += __shfl_down_sync(0xffffffffu, t, o);
        if (threadIdx.x == 0)
            g_pcopy[r] = 1.f / (1.f + __expf(-(t + bc[0])));
    }
}

__global__ void argmax_kernel(const float* __restrict__ src_map) {
    int task = blockIdx.x * 8 + (threadIdx.x >> 5);
    if (task >= SLEN * BATCH) return;
    int lane = threadIdx.x & 31;
    const float* p = src_map + (size_t)task * EXT;
    float best = -INFINITY; int bi = EXT;
    for (int e = lane; e < EXT; e += 32) {
        float v = p[e];
        if (v > best) { best = v; bi = e; }
    }
    for (int off = 16; off; off >>= 1) {
        float ov = __shfl_down_sync(0xffffffffu, best, off);
        int   oi = __shfl_down_sync(0xffffffffu, bi, off);
        if (ov > best || (ov == best && oi < bi)) { best = ov; bi = oi; }
    }
    if (lane == 0) g_idx[task] = bi;
}

// ---------------------------------------------------------------------------
// bf16 mma.sync GEMM: out[m, n] = exp(A.W^T + b) (PAD col -> 0),
// partial row sums into g_rowsum.
extern __shared__ char dyn_smem[];

__global__ __launch_bounds__(256, 1)
void gemm_tc_kernel(const __nv_bfloat16* __restrict__ A,   // (BT, DIM)
                    const __nv_bfloat16* __restrict__ W,   // (VOCAB, DIM)
                    const float* __restrict__ bias,
                    float* __restrict__ out) {
    const uint32_t sbase = smem_u32(dyn_smem);
    const int tid  = threadIdx.x;
    const int wid  = tid >> 5;
    const int lane = tid & 31;
    const int warp_m = wid & 3;        // 0..3  (64-row slice of 256)
    const int warp_n = wid >> 2;       // 0..1  (64-col slice of 128)
    const int m0 = blockIdx.x * BM;
    const int n0 = blockIdx.y * BN;

    const __nv_bfloat16* Abase = A + (size_t)m0 * DIM;
    const __nv_bfloat16* Wbase = W + (size_t)n0 * DIM;

    // loader: 384 rows x 8 chunks(16B) = 3072 chunks / 256 thr = 12 each
    auto load_stage = [&](int j) {
        uint32_t s = sbase + (uint32_t)(j % STAGES) * STAGE_BYTES;
        int k0 = j * BK;
#pragma unroll
        for (int i = 0; i < 12; i++) {
            int ch  = i * 256 + tid;              // 0..3071
            int row = ch >> 3;                    // 0..383
            int cc  = ch & 7;                     // 16B chunk in 128B row
            uint32_t off = (uint32_t)((cc * 16) ^ ((row & 7) << 4));
            if (row < BM) {
                cpasync16(s + (uint32_t)(row * 128) + off,
                          Abase + (size_t)row * DIM + k0 + cc * 8);
            } else {
                int br = row - BM;
                cpasync16(s + A_TILE_BYTES + (uint32_t)(br * 128)
                            + (uint32_t)((cc * 16) ^ ((br & 7) << 4)),
                          Wbase + (size_t)br * DIM + k0 + cc * 8);
            }
        }
        asm volatile("cp.async.commit_group;" ::: "memory");
    };

    float acc[4][8][4];
#pragma unroll
    for (int i = 0; i < 4; i++)
#pragma unroll
        for (int j = 0; j < 8; j++)
#pragma unroll
            for (int q = 0; q < 4; q++) acc[i][j][q] = 0.f;

    // per-lane ldmatrix addressing
    const int tile = lane >> 3, tr = lane & 7;
    // A (m16k16): lanes0-7 m0-7 k-lo, 8-15 m8-15 k-lo, 16-23 m0-7 k-hi, 24-31 m8-15 k-hi
    const int a_row0 = warp_m * 64 + (tile & 1) * 8 + tr;
    const int a_half = (tile >> 1) * 16;
    // B (n16k16): lanes0-7 n0-7 k-lo, 8-15 n0-7 k-hi, 16-23 n8-15 k-lo, 24-31 n8-15 k-hi
    const int b_row0 = warp_n * 64 + (tile >> 1) * 8 + tr;
    const int b_half = (tile & 1) * 16;

    for (int j = 0; j < STAGES; j++) load_stage(j);

    for (int j = 0; j < NCHUNK; j++) {
        if (j < NCHUNK - 2)
            asm volatile("cp.async.wait_group %0;" :: "n"(STAGES - 1) : "memory");
        else if (j == NCHUNK - 2)
            asm volatile("cp.async.wait_group %0;" :: "n"(1) : "memory");
        else
            asm volatile("cp.async.wait_group %0;" :: "n"(0) : "memory");
        __syncthreads();

        uint32_t sA = sbase + (uint32_t)(j % STAGES) * STAGE_BYTES;
        uint32_t sB = sA + A_TILE_BYTES;

#pragma unroll
        for (int ks = 0; ks < 4; ks++) {          // k16 steps within BK=64
            uint32_t a[4][4];
#pragma unroll
            for (int mt = 0; mt < 4; mt++) {
                int row = a_row0 + mt * 16;
                uint32_t col = (uint32_t)((ks * 32 + a_half) ^ ((row & 7) << 4));
                ldm_x4(a[mt], sA + (uint32_t)(row * 128) + col);
            }
            uint32_t bf[4][4];
#pragma unroll
            for (int bg = 0; bg < 4; bg++) {      // 4 n16 groups in 64
                int row = b_row0 + bg * 16;
                uint32_t col = (uint32_t)((ks * 32 + b_half) ^ ((row & 7) << 4));
                ldm_x4(bf[bg], sB + (uint32_t)(row * 128) + col);
            }
#pragma unroll
            for (int mt = 0; mt < 4; mt++)
#pragma unroll
                for (int bg = 0; bg < 4; bg++) {
                    mma_bf16(acc[mt][bg * 2 + 0], a[mt], bf[bg][0], bf[bg][1]);
                    mma_bf16(acc[mt][bg * 2 + 1], a[mt], bf[bg][2], bf[bg][3]);
                }
        }
        __syncthreads();
        if (j + STAGES < NCHUNK) load_stage(j + STAGES);
    }

    // ---- epilogue: bias + exp + store + row-sum ----
    const int g  = lane >> 2;          // 0..7
    const int q4 = lane & 3;
    float rs_lo[4], rs_hi[4];
#pragma unroll
    for (int mt = 0; mt < 4; mt++) { rs_lo[mt] = 0.f; rs_hi[mt] = 0.f; }

#pragma unroll
    for (int mt = 0; mt < 4; mt++) {
        int m_lo = m0 + warp_m * 64 + mt * 16 + g;
        int m_hi = m_lo + 8;
        float* row_lo = out + (size_t)m_lo * OUTW;
        float* row_hi = out + (size_t)m_hi * OUTW;
#pragma unroll
        for (int nt = 0; nt < 8; nt++) {
            int n = n0 + warp_n * 64 + nt * 8 + q4 * 2;
            float b0 = __ldg(&bias[n]);
            float b1 = __ldg(&bias[n + 1]);
            float e0 = __expf(acc[mt][nt][0] + b0);
            float e1 = __expf(acc[mt][nt][1] + b1);
            float e2 = __expf(acc[mt][nt][2] + b0);
            float e3 = __expf(acc[mt][nt][3] + b1);
            if (n == PAD_IDX)     { e0 = 0.f; e2 = 0.f; }
            if (n + 1 == PAD_IDX) { e1 = 0.f; e3 = 0.f; }
            *(float2*)(row_lo + n) = make_float2(e0, e1);
            *(float2*)(row_hi + n) = make_float2(e2, e3);
            rs_lo[mt] += e0 + e1;
            rs_hi[mt] += e2 + e3;
        }
    }
#pragma unroll
    for (int mt = 0; mt < 4; mt++) {
        float lo = rs_lo[mt], hi = rs_hi[mt];
        lo += __shfl_xor_sync(0xffffffffu, lo, 1);
        lo += __shfl_xor_sync(0xffffffffu, lo, 2);
        hi += __shfl_xor_sync(0xffffffffu, hi, 1);
        hi += __shfl_xor_sync(0xffffffffu, hi, 2);
        if (q4 == 0) {
            int m_lo = m0 + warp_m * 64 + mt * 16 + g;
            atomicAdd(&g_rowsum[m_lo], lo);
            atomicAdd(&g_rowsum[m_lo + 8], hi);
        }
    }
}

// ---------------------------------------------------------------------------
// out[r, 0:VOCAB] *= (1 - pcopy[r]) / rowsum[r]
__global__ __launch_bounds__(512)
void scale_kernel(float* __restrict__ out) {
    int r = blockIdx.x;
    float s = (1.f - g_pcopy[r]) / g_rowsum[r];
    float4* row = (float4*)(out + (size_t)r * OUTW);
    for (int i = threadIdx.x; i < VOCAB / 4; i += blockDim.x) {
        float4 v = row[i];
        v.x *= s; v.y *= s; v.z *= s; v.w *= s;
        row[i] = v;
    }
}

// ---------------------------------------------------------------------------
__global__ void copy_kernel(const float* __restrict__ attn,
                            float* __restrict__ out) {
    int r = blockIdx.x;
    int b = r % BATCH;               // rows are tlen-major: r = t*BATCH + b
    __shared__ float bins[EXT];
    for (int c = threadIdx.x; c < EXT; c += blockDim.x) bins[c] = 0.f;
    __syncthreads();
    const float* arow = attn + (size_t)r * SLEN;
    for (int s = threadIdx.x; s < SLEN; s += blockDim.x)
        atomicAdd(&bins[g_idx[s * BATCH + b]], arow[s]);
    __syncthreads();
    float pc = g_pcopy[r];
    float* orow = out + (size_t)r * OUTW + VOCAB;
    for (int c = threadIdx.x; c < EXT; c += blockDim.x)
        orow[c] = bins[c] * pc;
}

// ---------------------------------------------------------------------------
extern "C" void kernel_launch(void* const* d_in, const int* in_sizes, int n_in,
                              void* d_out, int out_size) {
    const float* hidden = (const float*)d_in[0];
    const float* attn   = (const float*)d_in[1];
    const float* srcmap = (const float*)d_in[2];
    const float* W      = (const float*)d_in[3];
    const float* b      = (const float*)d_in[4];
    const float* Wc     = (const float*)d_in[5];
    const float* bc     = (const float*)d_in[6];
    float* out = (float*)d_out;

    cudaFuncSetAttribute(gemm_tc_kernel,
                         cudaFuncAttributeMaxDynamicSharedMemorySize, SMEM_BYTES);

    __nv_bfloat16 *Wbv, *Abv;
    cudaGetSymbolAddress((void**)&Wbv, g_Wb);
    cudaGetSymbolAddress((void**)&Abv, g_Ab);

    init_kernel<<<(BT + 255) / 256, 256>>>();
    cvt_bf16_kernel<<<2048, 256>>>((const float4*)W, (uint2*)Wbv,
                                   (int)((size_t)VOCAB * DIM / 4));
    cvt_bf16_kernel<<<512, 256>>>((const float4*)hidden, (uint2*)Abv,
                                  (int)((size_t)BT * DIM / 4));
    pcopy_kernel<<<BT, 256>>>(hidden, Wc, bc);
    argmax_kernel<<<(SLEN * BATCH + 7) / 8, 256>>>(srcmap);

    dim3 grid(BT / BM, VOCAB / BN);   // (8, 250): waves share W slices in L2
    gemm_tc_kernel<<<grid, 256, SMEM_BYTES>>>(Abv, Wbv, b, out);

    scale_kernel<<<BT, 512>>>(out);
    copy_kernel<<<BT, 256>>>(attn, out);
}

// round 6
// speedup vs baseline: 6.9411x; 1.0718x over previous
#include <cuda_runtime.h>
#include <cuda_bf16.h>
#include <math.h>
#include <stdint.h>

// ---------------- problem constants ----------------
#define BATCH 32
#define TLEN 64
#define SLEN 400
#define DIM 1024
#define VOCAB 32000
#define EXT 600
#define BT (BATCH * TLEN)      // 2048 rows
#define OUTW (VOCAB + EXT)     // 32600
#define PAD_IDX 1

// ---------------- GEMM tiling (bf16) ----------------
#define BM 128
#define BN 128
#define BK 64                       // 64 bf16 = 128B rows
#define STAGES 3
#define NCHUNK (DIM / BK)           // 16
#define A_TILE_BYTES (BM * 128)     // 16 KB
#define B_TILE_BYTES (BN * 128)     // 16 KB
#define STAGE_BYTES (A_TILE_BYTES + B_TILE_BYTES)  // 32 KB
#define SMEM_BYTES (STAGES * STAGE_BYTES)          // 96 KB -> 2 CTAs/SM

// ---------------- scratch (device globals; no allocation allowed) ----------
__device__ float g_pcopy[BT];
__device__ float g_rowsum[BT];
__device__ int   g_idx[SLEN * BATCH];
__device__ __nv_bfloat16 g_Wb[(size_t)VOCAB * DIM];   // bf16 W (64 MB)
__device__ __nv_bfloat16 g_Ab[(size_t)BT * DIM];      // bf16 hidden (4 MB)

// ---------------- helpers ----------------
__device__ __forceinline__ uint32_t smem_u32(const void* p) {
    uint32_t a;
    asm("{ .reg .u64 t; cvta.to.shared.u64 t, %1; cvt.u32.u64 %0, t; }"
        : "=r"(a) : "l"(p));
    return a;
}

__device__ __forceinline__ void cpasync16(uint32_t dst, const void* src) {
    asm volatile("cp.async.cg.shared.global [%0], [%1], 16;"
                 :: "r"(dst), "l"(src) : "memory");
}

__device__ __forceinline__ void ldm_x4(uint32_t* r, uint32_t addr) {
    asm volatile("ldmatrix.sync.aligned.m8n8.x4.shared.b16 {%0,%1,%2,%3}, [%4];"
                 : "=r"(r[0]), "=r"(r[1]), "=r"(r[2]), "=r"(r[3]) : "r"(addr));
}

__device__ __forceinline__ void mma_bf16(float* c, const uint32_t* a,
                                         uint32_t b0, uint32_t b1) {
    asm volatile(
        "mma.sync.aligned.m16n8k16.row.col.f32.bf16.bf16.f32 "
        "{%0,%1,%2,%3}, {%4,%5,%6,%7}, {%8,%9}, {%0,%1,%2,%3};"
        : "+f"(c[0]), "+f"(c[1]), "+f"(c[2]), "+f"(c[3])
        : "r"(a[0]), "r"(a[1]), "r"(a[2]), "r"(a[3]), "r"(b0), "r"(b1));
}

// ---------------------------------------------------------------------------
// fp32 -> bf16 conversion (vectorized: float4 in, 8B out)
__global__ void cvt_bf16_kernel(const float4* __restrict__ src,
                                uint2* __restrict__ dst, int n4) {
    int stride = gridDim.x * blockDim.x;
    for (int i = blockIdx.x * blockDim.x + threadIdx.x; i < n4; i += stride) {
        float4 v = src[i];
        __nv_bfloat162 lo = __floats2bfloat162_rn(v.x, v.y);
        __nv_bfloat162 hi = __floats2bfloat162_rn(v.z, v.w);
        uint2 o;
        o.x = *(uint32_t*)&lo;
        o.y = *(uint32_t*)&hi;
        dst[i] = o;
    }
}

// ---------------------------------------------------------------------------
// p_copy + rowsum init (one block per row)
__global__ void pcopy_kernel(const float* __restrict__ hidden,
                             const float* __restrict__ Wc,
                             const float* __restrict__ bc) {
    int r = blockIdx.x;
    const float* h = hidden + (size_t)r * DIM;
    float s = 0.f;
    for (int k = threadIdx.x; k < DIM; k += blockDim.x) s += h[k] * Wc[k];
    __shared__ float red[32];
    for (int o = 16; o; o >>= 1) s += __shfl_down_sync(0xffffffffu, s, o);
    if ((threadIdx.x & 31) == 0) red[threadIdx.x >> 5] = s;
    __syncthreads();
    if (threadIdx.x < 32) {
        float t = (threadIdx.x < (blockDim.x >> 5)) ? red[threadIdx.x] : 0.f;
        for (int o = 16; o; o >>= 1) t += __shfl_down_sync(0xffffffffu, t, o);
        if (threadIdx.x == 0) {
            g_pcopy[r] = 1.f / (1.f + __expf(-(t + bc[0])));
            g_rowsum[r] = 0.f;
        }
    }
}

__global__ void argmax_kernel(const float* __restrict__ src_map) {
    int task = blockIdx.x * 8 + (threadIdx.x >> 5);
    if (task >= SLEN * BATCH) return;
    int lane = threadIdx.x & 31;
    const float* p = src_map + (size_t)task * EXT;
    float best = -INFINITY; int bi = EXT;
    for (int e = lane; e < EXT; e += 32) {
        float v = p[e];
        if (v > best) { best = v; bi = e; }
    }
    for (int off = 16; off; off >>= 1) {
        float ov = __shfl_down_sync(0xffffffffu, best, off);
        int   oi = __shfl_down_sync(0xffffffffu, bi, off);
        if (ov > best || (ov == best && oi < bi)) { best = ov; bi = oi; }
    }
    if (lane == 0) g_idx[task] = bi;
}

// ---------------------------------------------------------------------------
// bf16 mma.sync GEMM: out[m, n] = exp(A.W^T + b) (PAD col -> 0),
// partial row sums into g_rowsum.  128x128 CTA, 4 warps, 2 CTAs/SM.
extern __shared__ char dyn_smem[];

__global__ __launch_bounds__(128, 2)
void gemm_tc_kernel(const __nv_bfloat16* __restrict__ A,   // (BT, DIM)
                    const __nv_bfloat16* __restrict__ W,   // (VOCAB, DIM)
                    const float* __restrict__ bias,
                    float* __restrict__ out) {
    const uint32_t sbase = smem_u32(dyn_smem);
    const int tid  = threadIdx.x;
    const int wid  = tid >> 5;
    const int lane = tid & 31;
    const int warp_m = wid & 1;        // 0..1  (64-row slice of 128)
    const int warp_n = wid >> 1;       // 0..1  (64-col slice of 128)
    const int m0 = blockIdx.x * BM;
    const int n0 = blockIdx.y * BN;

    const __nv_bfloat16* Abase = A + (size_t)m0 * DIM;
    const __nv_bfloat16* Wbase = W + (size_t)n0 * DIM;

    // loader: 256 rows x 8 chunks(16B) = 2048 chunks / 128 thr = 16 each
    auto load_stage = [&](int j) {
        uint32_t s = sbase + (uint32_t)(j % STAGES) * STAGE_BYTES;
        int k0 = j * BK;
#pragma unroll
        for (int i = 0; i < 16; i++) {
            int ch  = i * 128 + tid;              // 0..2047
            int row = ch >> 3;                    // 0..255
            int cc  = ch & 7;                     // 16B chunk in 128B row
            if (row < BM) {
                uint32_t off = (uint32_t)((cc * 16) ^ ((row & 7) << 4));
                cpasync16(s + (uint32_t)(row * 128) + off,
                          Abase + (size_t)row * DIM + k0 + cc * 8);
            } else {
                int br = row - BM;
                uint32_t off = (uint32_t)((cc * 16) ^ ((br & 7) << 4));
                cpasync16(s + A_TILE_BYTES + (uint32_t)(br * 128) + off,
                          Wbase + (size_t)br * DIM + k0 + cc * 8);
            }
        }
        asm volatile("cp.async.commit_group;" ::: "memory");
    };

    float acc[4][8][4];
#pragma unroll
    for (int i = 0; i < 4; i++)
#pragma unroll
        for (int j = 0; j < 8; j++)
#pragma unroll
            for (int q = 0; q < 4; q++) acc[i][j][q] = 0.f;

    // per-lane ldmatrix addressing
    const int tile = lane >> 3, tr = lane & 7;
    const int a_row0 = warp_m * 64 + (tile & 1) * 8 + tr;
    const int a_half = (tile >> 1) * 16;
    const int b_row0 = warp_n * 64 + (tile >> 1) * 8 + tr;
    const int b_half = (tile & 1) * 16;

    for (int j = 0; j < STAGES; j++) load_stage(j);

    for (int j = 0; j < NCHUNK; j++) {
        if (j < NCHUNK - 2)
            asm volatile("cp.async.wait_group %0;" :: "n"(STAGES - 1) : "memory");
        else if (j == NCHUNK - 2)
            asm volatile("cp.async.wait_group %0;" :: "n"(1) : "memory");
        else
            asm volatile("cp.async.wait_group %0;" :: "n"(0) : "memory");
        __syncthreads();

        uint32_t sA = sbase + (uint32_t)(j % STAGES) * STAGE_BYTES;
        uint32_t sB = sA + A_TILE_BYTES;

#pragma unroll
        for (int ks = 0; ks < 4; ks++) {          // k16 steps within BK=64
            uint32_t a[4][4];
#pragma unroll
            for (int mt = 0; mt < 4; mt++) {
                int row = a_row0 + mt * 16;
                uint32_t col = (uint32_t)((ks * 32 + a_half) ^ ((row & 7) << 4));
                ldm_x4(a[mt], sA + (uint32_t)(row * 128) + col);
            }
            uint32_t bf[4][4];
#pragma unroll
            for (int bg = 0; bg < 4; bg++) {      // 4 n16 groups in 64
                int row = b_row0 + bg * 16;
                uint32_t col = (uint32_t)((ks * 32 + b_half) ^ ((row & 7) << 4));
                ldm_x4(bf[bg], sB + (uint32_t)(row * 128) + col);
            }
#pragma unroll
            for (int mt = 0; mt < 4; mt++)
#pragma unroll
                for (int bg = 0; bg < 4; bg++) {
                    mma_bf16(acc[mt][bg * 2 + 0], a[mt], bf[bg][0], bf[bg][1]);
                    mma_bf16(acc[mt][bg * 2 + 1], a[mt], bf[bg][2], bf[bg][3]);
                }
        }
        __syncthreads();
        if (j + STAGES < NCHUNK) load_stage(j + STAGES);
    }

    // ---- epilogue: bias + exp + store + row-sum ----
    const int g  = lane >> 2;          // 0..7
    const int q4 = lane & 3;
    float rs_lo[4], rs_hi[4];
#pragma unroll
    for (int mt = 0; mt < 4; mt++) { rs_lo[mt] = 0.f; rs_hi[mt] = 0.f; }

#pragma unroll
    for (int mt = 0; mt < 4; mt++) {
        int m_lo = m0 + warp_m * 64 + mt * 16 + g;
        int m_hi = m_lo + 8;
        float* row_lo = out + (size_t)m_lo * OUTW;
        float* row_hi = out + (size_t)m_hi * OUTW;
#pragma unroll
        for (int nt = 0; nt < 8; nt++) {
            int n = n0 + warp_n * 64 + nt * 8 + q4 * 2;
            float b0 = __ldg(&bias[n]);
            float b1 = __ldg(&bias[n + 1]);
            float e0 = __expf(acc[mt][nt][0] + b0);
            float e1 = __expf(acc[mt][nt][1] + b1);
            float e2 = __expf(acc[mt][nt][2] + b0);
            float e3 = __expf(acc[mt][nt][3] + b1);
            if (n == PAD_IDX)     { e0 = 0.f; e2 = 0.f; }
            if (n + 1 == PAD_IDX) { e1 = 0.f; e3 = 0.f; }
            *(float2*)(row_lo + n) = make_float2(e0, e1);
            *(float2*)(row_hi + n) = make_float2(e2, e3);
            rs_lo[mt] += e0 + e1;
            rs_hi[mt] += e2 + e3;
        }
    }
#pragma unroll
    for (int mt = 0; mt < 4; mt++) {
        float lo = rs_lo[mt], hi = rs_hi[mt];
        lo += __shfl_xor_sync(0xffffffffu, lo, 1);
        lo += __shfl_xor_sync(0xffffffffu, lo, 2);
        hi += __shfl_xor_sync(0xffffffffu, hi, 1);
        hi += __shfl_xor_sync(0xffffffffu, hi, 2);
        if (q4 == 0) {
            int m_lo = m0 + warp_m * 64 + mt * 16 + g;
            atomicAdd(&g_rowsum[m_lo], lo);
            atomicAdd(&g_rowsum[m_lo + 8], hi);
        }
    }
}

// ---------------------------------------------------------------------------
// Fused finish: scale softmax part + build copy-prob bins.  One block per row.
__global__ __launch_bounds__(512)
void finish_kernel(const float* __restrict__ attn,
                   float* __restrict__ out) {
    int r = blockIdx.x;
    int b = r % BATCH;               // rows are tlen-major: r = t*BATCH + b
    float pc = g_pcopy[r];
    float s = (1.f - pc) / g_rowsum[r];

    __shared__ float bins[EXT];
    for (int c = threadIdx.x; c < EXT; c += blockDim.x) bins[c] = 0.f;
    __syncthreads();
    const float* arow = attn + (size_t)r * SLEN;
    for (int si = threadIdx.x; si < SLEN; si += blockDim.x)
        atomicAdd(&bins[g_idx[si * BATCH + b]], arow[si]);

    // scale the vocab part while bin atomics drain
    float4* row = (float4*)(out + (size_t)r * OUTW);
    for (int i = threadIdx.x; i < VOCAB / 4; i += blockDim.x) {
        float4 v = row[i];
        v.x *= s; v.y *= s; v.z *= s; v.w *= s;
        row[i] = v;
    }
    __syncthreads();
    float* orow = out + (size_t)r * OUTW + VOCAB;
    for (int c = threadIdx.x; c < EXT; c += blockDim.x)
        orow[c] = bins[c] * pc;
}

// ---------------------------------------------------------------------------
extern "C" void kernel_launch(void* const* d_in, const int* in_sizes, int n_in,
                              void* d_out, int out_size) {
    const float* hidden = (const float*)d_in[0];
    const float* attn   = (const float*)d_in[1];
    const float* srcmap = (const float*)d_in[2];
    const float* W      = (const float*)d_in[3];
    const float* b      = (const float*)d_in[4];
    const float* Wc     = (const float*)d_in[5];
    const float* bc     = (const float*)d_in[6];
    float* out = (float*)d_out;

    cudaFuncSetAttribute(gemm_tc_kernel,
                         cudaFuncAttributeMaxDynamicSharedMemorySize, SMEM_BYTES);

    __nv_bfloat16 *Wbv, *Abv;
    cudaGetSymbolAddress((void**)&Wbv, g_Wb);
    cudaGetSymbolAddress((void**)&Abv, g_Ab);

    cvt_bf16_kernel<<<2048, 256>>>((const float4*)W, (uint2*)Wbv,
                                   (int)((size_t)VOCAB * DIM / 4));
    cvt_bf16_kernel<<<512, 256>>>((const float4*)hidden, (uint2*)Abv,
                                  (int)((size_t)BT * DIM / 4));
    pcopy_kernel<<<BT, 256>>>(hidden, Wc, bc);
    argmax_kernel<<<(SLEN * BATCH + 7) / 8, 256>>>(srcmap);

    dim3 grid(BT / BM, VOCAB / BN);   // (16, 250): waves share W slices in L2
    gemm_tc_kernel<<<grid, 128, SMEM_BYTES>>>(Abv, Wbv, b, out);

    finish_kernel<<<BT, 512>>>(attn, out);
}